// round 4
// baseline (speedup 1.0000x reference)
#include <cuda_runtime.h>

#define NN   8192
#define FIN  256
#define H1   128
#define H2   64
#define F2   128          // mean || log_std
#define EMAX 393216

// ---------------- small persistent scratch only ----------------
static __device__ float g_z[NN * H2];      // latent
static __device__ float g_dinv[NN];
static __device__ int   g_count[NN];
static __device__ int   g_beg[NN];
static __device__ int   g_end[NN];
static __device__ int   g_cursor[NN];
static __device__ int   g_total;
static __device__ int   g_is64;            // edge_index dtype flag
static __device__ int   g_csr[EMAX];       // src ids grouped by dst (order irrelevant)
static __device__ float g_bias2[F2];       // bm || bs

// large intermediates live inside d_out (64M floats); all consumed before zzt overwrites
#define OFF_HLIN 0
#define OFF_H    (1 << 20)
#define OFF_L2   (2 << 20)
#define OFF_MS   (3 << 20)

// ---------------- edge_index dtype sniff ----------------
// If the buffer is int64 (values < 2^32), every odd 32-bit word is 0.
// If it is int32 (random node ids), odd words are ~never all zero.
static __global__ void vg_sniff(const unsigned* __restrict__ ei_w) {
    __shared__ int any_nonzero;
    if (threadIdx.x == 0) any_nonzero = 0;
    __syncthreads();
    unsigned w = ei_w[2 * threadIdx.x + 1];   // high word if int64
    if (w != 0) atomicOr(&any_nonzero, 1);
    __syncthreads();
    if (threadIdx.x == 0) g_is64 = any_nonzero ? 0 : 1;
}

static __device__ __forceinline__ int edge_at(const void* ei, int E, int idx) {
    int v;
    if (g_is64) v = (int)((const long long*)ei)[idx];
    else        v = ((const int*)ei)[idx];
    // clamp: never trap even on unexpected data
    return (v < 0) ? 0 : (v >= NN ? NN - 1 : v);
}

// ---------------- graph preprocessing ----------------
static __global__ void vg_count_zero() {
    int i = blockIdx.x * blockDim.x + threadIdx.x;
    if (i < NN) g_count[i] = 0;
    if (i == 0) g_total = 0;
}

static __global__ void vg_count_edges(const void* __restrict__ ei, int E) {
    int e = blockIdx.x * blockDim.x + threadIdx.x;
    if (e < E) atomicAdd(&g_count[edge_at(ei, E, E + e)], 1);   // dst
}

// per-node: dinv and CSR range allocation (order-free, no scan needed)
static __global__ void vg_alloc_ranges() {
    int i = blockIdx.x * blockDim.x + threadIdx.x;
    if (i >= NN) return;
    int c = g_count[i];
    g_dinv[i] = rsqrtf((float)(c + 1));     // +1 self loop
    int o = atomicAdd(&g_total, c);
    g_beg[i] = o;
    g_cursor[i] = o;
    g_end[i] = o + c;
}

static __global__ void vg_scatter_edges(const void* __restrict__ ei, int E) {
    int e = blockIdx.x * blockDim.x + threadIdx.x;
    if (e < E) {
        int d = edge_at(ei, E, E + e);      // dst
        int s = edge_at(ei, E, e);          // src
        int pos = atomicAdd(&g_cursor[d], 1);
        if (pos < EMAX) g_csr[pos] = s;
    }
}

static __global__ void vg_bias2(const float* __restrict__ bm, const float* __restrict__ bs) {
    int i = threadIdx.x;  // 128 threads
    g_bias2[i] = (i < H2) ? bm[i] : bs[i - H2];
}

// ---------------- GCN aggregation: one warp per dst node, 128 features ----------------
static __device__ __forceinline__ void agg_body(const float* __restrict__ lin,
                                                const float* __restrict__ bias,
                                                float* __restrict__ out) {
    int warp = (blockIdx.x * blockDim.x + threadIdx.x) >> 5;
    int lane = threadIdx.x & 31;
    if (warp >= NN) return;
    int d = warp;
    int p = g_beg[d], end = g_end[d];
    float did = g_dinv[d];
    float ax = 0.f, ay = 0.f, az = 0.f, aw = 0.f;
    int c4 = lane * 4;
    for (; p + 3 < end; p += 4) {
        int s0 = g_csr[p], s1 = g_csr[p + 1], s2 = g_csr[p + 2], s3 = g_csr[p + 3];
        float w0 = did * g_dinv[s0];
        float w1 = did * g_dinv[s1];
        float w2 = did * g_dinv[s2];
        float w3 = did * g_dinv[s3];
        float4 v0 = *(const float4*)&lin[s0 * H1 + c4];
        float4 v1 = *(const float4*)&lin[s1 * H1 + c4];
        float4 v2 = *(const float4*)&lin[s2 * H1 + c4];
        float4 v3 = *(const float4*)&lin[s3 * H1 + c4];
        ax += w0 * v0.x; ay += w0 * v0.y; az += w0 * v0.z; aw += w0 * v0.w;
        ax += w1 * v1.x; ay += w1 * v1.y; az += w1 * v1.z; aw += w1 * v1.w;
        ax += w2 * v2.x; ay += w2 * v2.y; az += w2 * v2.z; aw += w2 * v2.w;
        ax += w3 * v3.x; ay += w3 * v3.y; az += w3 * v3.z; aw += w3 * v3.w;
    }
    for (; p < end; p++) {
        int s = g_csr[p];
        float w = did * g_dinv[s];
        float4 v = *(const float4*)&lin[s * H1 + c4];
        ax += w * v.x; ay += w * v.y; az += w * v.z; aw += w * v.w;
    }
    {   // self loop + bias
        float w = did * did;
        float4 v = *(const float4*)&lin[d * H1 + c4];
        float4 b = *(const float4*)&bias[c4];
        ax = ax + w * v.x + b.x;
        ay = ay + w * v.y + b.y;
        az = az + w * v.z + b.z;
        aw = aw + w * v.w + b.w;
    }
    float4 r = make_float4(ax, ay, az, aw);
    *(float4*)&out[d * H1 + c4] = r;
}

static __global__ void __launch_bounds__(256)
vg_agg1(const float* __restrict__ b0, float* __restrict__ scratch) {
    agg_body(scratch + OFF_HLIN, b0, scratch + OFF_H);
}

static __global__ void __launch_bounds__(256)
vg_agg2(float* __restrict__ scratch) {
    agg_body(scratch + OFF_L2, g_bias2, scratch + OFF_MS);
}

// ---------------- fp32 SGEMM body: C[M,N] = A[M,K] @ B[K,N] ----------------
template <int BM, int BN, int BK, int TM, int TN>
static __device__ __forceinline__ void sgemm_body(const float* __restrict__ A,
                                                  const float* __restrict__ B,
                                                  float* __restrict__ C,
                                                  int K, int ldb, int ldc, int col0) {
    constexpr int THREADS = (BM / TM) * (BN / TN);
    __shared__ float As[BK][BM + 4];
    __shared__ float Bs[BK][BN];
    int row0 = blockIdx.x * BM;
    int tid = threadIdx.x;
    int tcol = tid % (BN / TN);
    int trow = tid / (BN / TN);
    float acc[TM][TN] = {};
    for (int k0 = 0; k0 < K; k0 += BK) {
        for (int i = tid; i < BM * BK / 4; i += THREADS) {
            int m = i / (BK / 4);
            int kk = (i % (BK / 4)) * 4;
            float4 v = *(const float4*)&A[(row0 + m) * K + k0 + kk];
            As[kk + 0][m] = v.x; As[kk + 1][m] = v.y;
            As[kk + 2][m] = v.z; As[kk + 3][m] = v.w;
        }
        for (int i = tid; i < BK * BN / 4; i += THREADS) {
            int kk = i / (BN / 4);
            int n = (i % (BN / 4)) * 4;
            *(float4*)&Bs[kk][n] = *(const float4*)&B[(k0 + kk) * ldb + n];
        }
        __syncthreads();
        #pragma unroll
        for (int kk = 0; kk < BK; kk++) {
            float a[TM], b[TN];
            #pragma unroll
            for (int i = 0; i < TM; i++) a[i] = As[kk][trow * TM + i];
            #pragma unroll
            for (int j = 0; j < TN; j++) b[j] = Bs[kk][tcol * TN + j];
            #pragma unroll
            for (int i = 0; i < TM; i++)
                #pragma unroll
                for (int j = 0; j < TN; j++)
                    acc[i][j] += a[i] * b[j];
        }
        __syncthreads();
    }
    #pragma unroll
    for (int i = 0; i < TM; i++) {
        #pragma unroll
        for (int j = 0; j < TN; j += 4) {
            float4 v = make_float4(acc[i][j], acc[i][j + 1], acc[i][j + 2], acc[i][j + 3]);
            *(float4*)&C[(row0 + trow * TM + i) * ldc + col0 + tcol * TN + j] = v;
        }
    }
}

// layer-1 GEMM: scratch[HLIN] = features @ W0   (K=256, N=128)
static __global__ void __launch_bounds__(256)
vg_gemm1(const float* __restrict__ features, const float* __restrict__ W0,
         float* __restrict__ scratch) {
    sgemm_body<64, 128, 32, 4, 8>(features, W0, scratch + OFF_HLIN, FIN, H1, H1, 0);
}

// layer-2 GEMM (both heads): scratch[L2][:, :64] = h@Wm ; [:, 64:] = h@Ws
static __global__ void __launch_bounds__(256)
vg_gemm2(const float* __restrict__ Wm, const float* __restrict__ Ws,
         float* __restrict__ scratch) {
    const float* B = (blockIdx.y == 0) ? Wm : Ws;
    sgemm_body<64, 64, 32, 4, 4>(scratch + OFF_H, B, scratch + OFF_L2, H1, H2, F2,
                                 blockIdx.y * H2);
}

// ---------------- z = mean + noise * exp(log_std) ----------------
static __global__ void vg_zk(const float* __restrict__ noise,
                             const float* __restrict__ scratch) {
    int i = blockIdx.x * blockDim.x + threadIdx.x;
    if (i >= NN * H2) return;
    int node = i >> 6;
    int f = i & 63;
    const float* ms = scratch + OFF_MS;
    float m  = ms[node * F2 + f];
    float ls = ms[node * F2 + H2 + f];
    g_z[i] = m + noise[i] * expf(ls);
}

// ---------------- C = sigmoid(Z @ Z^T), symmetric: upper blocks + mirror ----------------
static __global__ void __launch_bounds__(256)
vg_zzt(float* __restrict__ C) {
    int bi = blockIdx.y, bj = blockIdx.x;
    if (bj < bi) return;
    __shared__ float As[32][132];
    __shared__ float Bs[32][132];
    int tid = threadIdx.x;
    int trow = tid / 16;
    int tcol = tid % 16;
    int ri = bi * 128, rj = bj * 128;
    float acc[8][8] = {};
    for (int k0 = 0; k0 < H2; k0 += 32) {
        for (int i = tid; i < 128 * 8; i += 256) {   // 128 rows x 8 float4 along k
            int m = i >> 3;
            int kk = (i & 7) * 4;
            float4 a = *(const float4*)&g_z[(ri + m) * H2 + k0 + kk];
            As[kk + 0][m] = a.x; As[kk + 1][m] = a.y;
            As[kk + 2][m] = a.z; As[kk + 3][m] = a.w;
            float4 b = *(const float4*)&g_z[(rj + m) * H2 + k0 + kk];
            Bs[kk + 0][m] = b.x; Bs[kk + 1][m] = b.y;
            Bs[kk + 2][m] = b.z; Bs[kk + 3][m] = b.w;
        }
        __syncthreads();
        #pragma unroll
        for (int kk = 0; kk < 32; kk++) {
            float a[8], b[8];
            #pragma unroll
            for (int i = 0; i < 8; i++) a[i] = As[kk][trow * 8 + i];
            #pragma unroll
            for (int j = 0; j < 8; j++) b[j] = Bs[kk][tcol * 8 + j];
            #pragma unroll
            for (int i = 0; i < 8; i++)
                #pragma unroll
                for (int j = 0; j < 8; j++)
                    acc[i][j] += a[i] * b[j];
        }
        __syncthreads();
    }
    float sig[8][8];
    #pragma unroll
    for (int i = 0; i < 8; i++)
        #pragma unroll
        for (int j = 0; j < 8; j++) {
            float v = acc[i][j];
            float r = 1.0f / (1.0f + __expf(-v));
            sig[i][j] = (r == r) ? r : 0.0f;
        }
    #pragma unroll
    for (int i = 0; i < 8; i++) {
        int row = ri + trow * 8 + i;
        #pragma unroll
        for (int j = 0; j < 8; j += 4) {
            float4 v = make_float4(sig[i][j], sig[i][j + 1], sig[i][j + 2], sig[i][j + 3]);
            *(float4*)&C[(long long)row * NN + rj + tcol * 8 + j] = v;
        }
    }
    if (bi != bj) {
        #pragma unroll
        for (int j = 0; j < 8; j++) {
            int row = rj + tcol * 8 + j;
            float4 v0 = make_float4(sig[0][j], sig[1][j], sig[2][j], sig[3][j]);
            float4 v1 = make_float4(sig[4][j], sig[5][j], sig[6][j], sig[7][j]);
            *(float4*)&C[(long long)row * NN + ri + trow * 8 + 0] = v0;
            *(float4*)&C[(long long)row * NN + ri + trow * 8 + 4] = v1;
        }
    }
}

// ---------------- launch: kernel launches ONLY ----------------
extern "C" void kernel_launch(void* const* d_in, const int* in_sizes, int n_in,
                              void* d_out, int out_size) {
    const float* features = (const float*)d_in[0];
    const void*  ei       = d_in[1];                  // int32 or int64, sniffed on device
    const float* noise    = (const float*)d_in[2];
    const float* W0       = (const float*)d_in[3];
    const float* b0       = (const float*)d_in[4];
    const float* Wm       = (const float*)d_in[5];
    const float* bm       = (const float*)d_in[6];
    const float* Ws       = (const float*)d_in[7];
    const float* bs       = (const float*)d_in[8];
    int E = in_sizes[1] / 2;
    float* out = (float*)d_out;

    int eb = (E + 255) / 256;

    // detect edge_index dtype, then build CSR by dst
    vg_sniff<<<1, 256>>>((const unsigned*)ei);
    vg_count_zero<<<NN / 256, 256>>>();
    vg_count_edges<<<eb, 256>>>(ei, E);
    vg_alloc_ranges<<<NN / 256, 256>>>();
    vg_scatter_edges<<<eb, 256>>>(ei, E);

    // layer 1: h = agg(X @ W0) + b0
    vg_gemm1<<<dim3(NN / 64, 1), 256>>>(features, W0, out);
    vg_agg1<<<NN / 8, 256>>>(b0, out);

    // layer 2 (fused mean/log_std): l2 = h @ [Wm | Ws]; ms = agg(l2) + [bm | bs]
    vg_gemm2<<<dim3(NN / 64, 2), 256>>>(Wm, Ws, out);
    vg_bias2<<<1, 128>>>(bm, bs);
    vg_agg2<<<NN / 8, 256>>>(out);

    // reparameterize: z = mean + noise * exp(log_std)
    vg_zk<<<NN * H2 / 256, 256>>>(noise, out);

    // adj_rec = sigmoid(z @ z^T) with symmetry (overwrites all of d_out)
    vg_zzt<<<dim3(64, 64), 256>>>(out);
}

// round 5
// speedup vs baseline: 1.2959x; 1.2959x over previous
#include <cuda_runtime.h>
#include <cuda_bf16.h>

#define NN   8192
#define FIN  256
#define H1   128
#define H2   64
#define F2   128          // mean || log_std
#define K3   192          // hi|hi|lo split K
#define EMAX 393216

// ---------------- small persistent scratch only ----------------
static __device__ float g_dinv[NN];
static __device__ int   g_count[NN];
static __device__ int   g_beg[NN];
static __device__ int   g_end[NN];
static __device__ int   g_cursor[NN];
static __device__ int   g_total;
static __device__ int   g_is64;            // edge_index dtype flag
static __device__ int   g_csr[EMAX];       // src ids grouped by dst (order irrelevant)
static __device__ float g_bias2[F2];       // bm || bs
static __device__ __nv_bfloat16 g_za[NN * K3];   // [hi | hi | lo]
static __device__ __nv_bfloat16 g_zb[NN * K3];   // [hi | lo | hi]

// large fp32 intermediates live inside d_out (64M floats); consumed before zzt overwrites
#define OFF_HLIN 0
#define OFF_H    (1 << 20)
#define OFF_L2   (2 << 20)
#define OFF_MS   (3 << 20)

// ---------------- edge_index dtype sniff ----------------
static __global__ void vg_sniff(const unsigned* __restrict__ ei_w) {
    __shared__ int any_nonzero;
    if (threadIdx.x == 0) any_nonzero = 0;
    __syncthreads();
    unsigned w = ei_w[2 * threadIdx.x + 1];   // high word if int64
    if (w != 0) atomicOr(&any_nonzero, 1);
    __syncthreads();
    if (threadIdx.x == 0) g_is64 = any_nonzero ? 0 : 1;
}

static __device__ __forceinline__ int edge_at(const void* ei, int E, int idx) {
    int v;
    if (g_is64) v = (int)((const long long*)ei)[idx];
    else        v = ((const int*)ei)[idx];
    return (v < 0) ? 0 : (v >= NN ? NN - 1 : v);
}

// ---------------- graph preprocessing ----------------
static __global__ void vg_count_zero() {
    int i = blockIdx.x * blockDim.x + threadIdx.x;
    if (i < NN) g_count[i] = 0;
    if (i == 0) g_total = 0;
}

static __global__ void vg_count_edges(const void* __restrict__ ei, int E) {
    int e = blockIdx.x * blockDim.x + threadIdx.x;
    if (e < E) atomicAdd(&g_count[edge_at(ei, E, E + e)], 1);   // dst
}

static __global__ void vg_alloc_ranges() {
    int i = blockIdx.x * blockDim.x + threadIdx.x;
    if (i >= NN) return;
    int c = g_count[i];
    g_dinv[i] = rsqrtf((float)(c + 1));     // +1 self loop
    int o = atomicAdd(&g_total, c);
    g_beg[i] = o;
    g_cursor[i] = o;
    g_end[i] = o + c;
}

static __global__ void vg_scatter_edges(const void* __restrict__ ei, int E) {
    int e = blockIdx.x * blockDim.x + threadIdx.x;
    if (e < E) {
        int d = edge_at(ei, E, E + e);
        int s = edge_at(ei, E, e);
        int pos = atomicAdd(&g_cursor[d], 1);
        if (pos < EMAX) g_csr[pos] = s;
    }
}

static __global__ void vg_bias2(const float* __restrict__ bm, const float* __restrict__ bs) {
    int i = threadIdx.x;  // 128 threads
    g_bias2[i] = (i < H2) ? bm[i] : bs[i - H2];
}

// ---------------- GCN aggregation: one warp per dst node, 128 features ----------------
static __device__ __forceinline__ void agg_body(const float* __restrict__ lin,
                                                const float* __restrict__ bias,
                                                float* __restrict__ out) {
    int warp = (blockIdx.x * blockDim.x + threadIdx.x) >> 5;
    int lane = threadIdx.x & 31;
    if (warp >= NN) return;
    int d = warp;
    int p = g_beg[d], end = g_end[d];
    float did = g_dinv[d];
    float ax = 0.f, ay = 0.f, az = 0.f, aw = 0.f;
    int c4 = lane * 4;
    for (; p + 3 < end; p += 4) {
        int s0 = g_csr[p], s1 = g_csr[p + 1], s2 = g_csr[p + 2], s3 = g_csr[p + 3];
        float w0 = did * g_dinv[s0];
        float w1 = did * g_dinv[s1];
        float w2 = did * g_dinv[s2];
        float w3 = did * g_dinv[s3];
        float4 v0 = *(const float4*)&lin[s0 * H1 + c4];
        float4 v1 = *(const float4*)&lin[s1 * H1 + c4];
        float4 v2 = *(const float4*)&lin[s2 * H1 + c4];
        float4 v3 = *(const float4*)&lin[s3 * H1 + c4];
        ax += w0 * v0.x; ay += w0 * v0.y; az += w0 * v0.z; aw += w0 * v0.w;
        ax += w1 * v1.x; ay += w1 * v1.y; az += w1 * v1.z; aw += w1 * v1.w;
        ax += w2 * v2.x; ay += w2 * v2.y; az += w2 * v2.z; aw += w2 * v2.w;
        ax += w3 * v3.x; ay += w3 * v3.y; az += w3 * v3.z; aw += w3 * v3.w;
    }
    for (; p < end; p++) {
        int s = g_csr[p];
        float w = did * g_dinv[s];
        float4 v = *(const float4*)&lin[s * H1 + c4];
        ax += w * v.x; ay += w * v.y; az += w * v.z; aw += w * v.w;
    }
    {   // self loop + bias
        float w = did * did;
        float4 v = *(const float4*)&lin[d * H1 + c4];
        float4 b = *(const float4*)&bias[c4];
        ax = ax + w * v.x + b.x;
        ay = ay + w * v.y + b.y;
        az = az + w * v.z + b.z;
        aw = aw + w * v.w + b.w;
    }
    float4 r = make_float4(ax, ay, az, aw);
    *(float4*)&out[d * H1 + c4] = r;
}

static __global__ void __launch_bounds__(256)
vg_agg1(const float* __restrict__ b0, float* __restrict__ scratch) {
    agg_body(scratch + OFF_HLIN, b0, scratch + OFF_H);
}

static __global__ void __launch_bounds__(256)
vg_agg2(float* __restrict__ scratch) {
    agg_body(scratch + OFF_L2, g_bias2, scratch + OFF_MS);
}

// ---------------- fp32 SGEMM body: C[M,N] = A[M,K] @ B[K,N] ----------------
template <int BM, int BN, int BK, int TM, int TN>
static __device__ __forceinline__ void sgemm_body(const float* __restrict__ A,
                                                  const float* __restrict__ B,
                                                  float* __restrict__ C,
                                                  int K, int ldb, int ldc, int col0) {
    constexpr int THREADS = (BM / TM) * (BN / TN);
    __shared__ float As[BK][BM + 4];
    __shared__ float Bs[BK][BN];
    int row0 = blockIdx.x * BM;
    int tid = threadIdx.x;
    int tcol = tid % (BN / TN);
    int trow = tid / (BN / TN);
    float acc[TM][TN] = {};
    for (int k0 = 0; k0 < K; k0 += BK) {
        for (int i = tid; i < BM * BK / 4; i += THREADS) {
            int m = i / (BK / 4);
            int kk = (i % (BK / 4)) * 4;
            float4 v = *(const float4*)&A[(row0 + m) * K + k0 + kk];
            As[kk + 0][m] = v.x; As[kk + 1][m] = v.y;
            As[kk + 2][m] = v.z; As[kk + 3][m] = v.w;
        }
        for (int i = tid; i < BK * BN / 4; i += THREADS) {
            int kk = i / (BN / 4);
            int n = (i % (BN / 4)) * 4;
            *(float4*)&Bs[kk][n] = *(const float4*)&B[(k0 + kk) * ldb + n];
        }
        __syncthreads();
        #pragma unroll
        for (int kk = 0; kk < BK; kk++) {
            float a[TM], b[TN];
            #pragma unroll
            for (int i = 0; i < TM; i++) a[i] = As[kk][trow * TM + i];
            #pragma unroll
            for (int j = 0; j < TN; j++) b[j] = Bs[kk][tcol * TN + j];
            #pragma unroll
            for (int i = 0; i < TM; i++)
                #pragma unroll
                for (int j = 0; j < TN; j++)
                    acc[i][j] += a[i] * b[j];
        }
        __syncthreads();
    }
    #pragma unroll
    for (int i = 0; i < TM; i++) {
        #pragma unroll
        for (int j = 0; j < TN; j += 4) {
            float4 v = make_float4(acc[i][j], acc[i][j + 1], acc[i][j + 2], acc[i][j + 3]);
            *(float4*)&C[(row0 + trow * TM + i) * ldc + col0 + tcol * TN + j] = v;
        }
    }
}

static __global__ void __launch_bounds__(256)
vg_gemm1(const float* __restrict__ features, const float* __restrict__ W0,
         float* __restrict__ scratch) {
    sgemm_body<64, 128, 32, 4, 8>(features, W0, scratch + OFF_HLIN, FIN, H1, H1, 0);
}

static __global__ void __launch_bounds__(256)
vg_gemm2(const float* __restrict__ Wm, const float* __restrict__ Ws,
         float* __restrict__ scratch) {
    const float* B = (blockIdx.y == 0) ? Wm : Ws;
    sgemm_body<64, 64, 32, 4, 4>(scratch + OFF_H, B, scratch + OFF_L2, H1, H2, F2,
                                 blockIdx.y * H2);
}

// ---------------- z = mean + noise*exp(log_std); split into bf16 hi/lo packs ----------------
static __global__ void vg_zsplit(const float* __restrict__ noise,
                                 const float* __restrict__ scratch) {
    int i = blockIdx.x * blockDim.x + threadIdx.x;
    if (i >= NN * H2) return;
    int node = i >> 6;
    int f = i & 63;
    const float* ms = scratch + OFF_MS;
    float m  = ms[node * F2 + f];
    float ls = ms[node * F2 + H2 + f];
    float z = m + noise[i] * expf(ls);
    __nv_bfloat16 hi = __float2bfloat16(z);
    __nv_bfloat16 lo = __float2bfloat16(z - __bfloat162float(hi));
    int base = node * K3 + f;
    g_za[base]       = hi;   // A = [hi | hi | lo]
    g_za[base + 64]  = hi;
    g_za[base + 128] = lo;
    g_zb[base]       = hi;   // B = [hi | lo | hi]
    g_zb[base + 64]  = lo;
    g_zb[base + 128] = hi;
}

// ---------------- C = sigmoid(Z Z^T) via bf16 mma.sync, K=192 split ----------------
// block: 128x128 tile, 256 threads = 8 warps (4x2); warp tile 32x64.
#define ZBK 32
#define ZPAD 8
static __global__ void __launch_bounds__(256)
vg_zzt_mma(float* __restrict__ C) {
    int bi = blockIdx.y, bj = blockIdx.x;
    if (bj < bi) return;
    __shared__ __nv_bfloat16 As[128][ZBK + ZPAD];
    __shared__ __nv_bfloat16 Bs[128][ZBK + ZPAD];
    int tid = threadIdx.x;
    int wid = tid >> 5;
    int lane = tid & 31;
    int wm = wid >> 1;          // 0..3
    int wn = wid & 1;           // 0..1
    int g  = lane >> 2;         // 0..7
    int tg = lane & 3;          // 0..3
    int ri = bi * 128, rj = bj * 128;

    float acc[2][8][4];
    #pragma unroll
    for (int a = 0; a < 2; a++)
        #pragma unroll
        for (int b = 0; b < 8; b++)
            #pragma unroll
            for (int c = 0; c < 4; c++) acc[a][b][c] = 0.f;

    for (int k0 = 0; k0 < K3; k0 += ZBK) {
        // load tiles: 128 rows x 32 bf16 = 4 float4 per row; 512 float4s, 256 threads -> 2 each
        #pragma unroll
        for (int r = 0; r < 2; r++) {
            int i = tid + r * 256;
            int m = i >> 2;
            int kk = (i & 3) * 8;
            *(float4*)&As[m][kk] = *(const float4*)&g_za[(ri + m) * K3 + k0 + kk];
            *(float4*)&Bs[m][kk] = *(const float4*)&g_zb[(rj + m) * K3 + k0 + kk];
        }
        __syncthreads();
        #pragma unroll
        for (int kk = 0; kk < ZBK; kk += 16) {
            // A fragments for 2 m-tiles
            unsigned a0[2], a1[2], a2[2], a3[2];
            #pragma unroll
            for (int mi = 0; mi < 2; mi++) {
                int row = 32 * wm + 16 * mi;
                a0[mi] = *(const unsigned*)&As[row + g    ][kk + 2 * tg];
                a1[mi] = *(const unsigned*)&As[row + g + 8][kk + 2 * tg];
                a2[mi] = *(const unsigned*)&As[row + g    ][kk + 2 * tg + 8];
                a3[mi] = *(const unsigned*)&As[row + g + 8][kk + 2 * tg + 8];
            }
            #pragma unroll
            for (int nj = 0; nj < 8; nj++) {
                int col = 64 * wn + 8 * nj + g;
                unsigned b0 = *(const unsigned*)&Bs[col][kk + 2 * tg];
                unsigned b1 = *(const unsigned*)&Bs[col][kk + 2 * tg + 8];
                #pragma unroll
                for (int mi = 0; mi < 2; mi++) {
                    asm volatile(
                        "mma.sync.aligned.m16n8k16.row.col.f32.bf16.bf16.f32 "
                        "{%0,%1,%2,%3}, {%4,%5,%6,%7}, {%8,%9}, {%0,%1,%2,%3};"
                        : "+f"(acc[mi][nj][0]), "+f"(acc[mi][nj][1]),
                          "+f"(acc[mi][nj][2]), "+f"(acc[mi][nj][3])
                        : "r"(a0[mi]), "r"(a1[mi]), "r"(a2[mi]), "r"(a3[mi]),
                          "r"(b0), "r"(b1));
                }
            }
        }
        __syncthreads();
    }

    // sigmoid + nan_to_num
    #pragma unroll
    for (int mi = 0; mi < 2; mi++)
        #pragma unroll
        for (int nj = 0; nj < 8; nj++)
            #pragma unroll
            for (int c = 0; c < 4; c++) {
                float v = acc[mi][nj][c];
                float r = 1.0f / (1.0f + __expf(-v));
                acc[mi][nj][c] = (r == r) ? r : 0.0f;
            }

    // normal store (bi, bj): c0,c1 at (row, col..col+1); c2,c3 at (row+8, ...)
    #pragma unroll
    for (int mi = 0; mi < 2; mi++) {
        int row = ri + 32 * wm + 16 * mi + g;
        #pragma unroll
        for (int nj = 0; nj < 8; nj++) {
            int col = rj + 64 * wn + 8 * nj + 2 * tg;
            *(float2*)&C[(long long)row * NN + col] =
                make_float2(acc[mi][nj][0], acc[mi][nj][1]);
            *(float2*)&C[(long long)(row + 8) * NN + col] =
                make_float2(acc[mi][nj][2], acc[mi][nj][3]);
        }
    }
    // mirrored store (bj, bi): transpose coordinates
    if (bi != bj) {
        #pragma unroll
        for (int mi = 0; mi < 2; mi++) {
            int colm = ri + 32 * wm + 16 * mi + g;   // becomes column
            #pragma unroll
            for (int nj = 0; nj < 8; nj++) {
                int rowm = rj + 64 * wn + 8 * nj + 2 * tg;  // becomes row
                C[(long long)rowm * NN + colm]           = acc[mi][nj][0];
                C[(long long)(rowm + 1) * NN + colm]     = acc[mi][nj][1];
                C[(long long)rowm * NN + colm + 8]       = acc[mi][nj][2];
                C[(long long)(rowm + 1) * NN + colm + 8] = acc[mi][nj][3];
            }
        }
    }
}

// ---------------- launch: kernel launches ONLY ----------------
extern "C" void kernel_launch(void* const* d_in, const int* in_sizes, int n_in,
                              void* d_out, int out_size) {
    const float* features = (const float*)d_in[0];
    const void*  ei       = d_in[1];
    const float* noise    = (const float*)d_in[2];
    const float* W0       = (const float*)d_in[3];
    const float* b0       = (const float*)d_in[4];
    const float* Wm       = (const float*)d_in[5];
    const float* bm       = (const float*)d_in[6];
    const float* Ws       = (const float*)d_in[7];
    const float* bs       = (const float*)d_in[8];
    int E = in_sizes[1] / 2;
    float* out = (float*)d_out;

    int eb = (E + 255) / 256;

    // detect edge_index dtype, then build CSR by dst
    vg_sniff<<<1, 256>>>((const unsigned*)ei);
    vg_count_zero<<<NN / 256, 256>>>();
    vg_count_edges<<<eb, 256>>>(ei, E);
    vg_alloc_ranges<<<NN / 256, 256>>>();
    vg_scatter_edges<<<eb, 256>>>(ei, E);

    // layer 1: h = agg(X @ W0) + b0
    vg_gemm1<<<dim3(NN / 64, 1), 256>>>(features, W0, out);
    vg_agg1<<<NN / 8, 256>>>(b0, out);

    // layer 2 (fused mean/log_std): l2 = h @ [Wm | Ws]; ms = agg(l2) + [bm | bs]
    vg_gemm2<<<dim3(NN / 64, 2), 256>>>(Wm, Ws, out);
    vg_bias2<<<1, 128>>>(bm, bs);
    vg_agg2<<<NN / 8, 256>>>(out);

    // reparameterize + bf16 hi/lo split packs
    vg_zsplit<<<NN * H2 / 256, 256>>>(noise, out);

    // adj_rec = sigmoid(z @ z^T), tensor cores, symmetric
    vg_zzt_mma<<<dim3(64, 64), 256>>>(out);
}